// round 17
// baseline (speedup 1.0000x reference)
#include <cuda_runtime.h>
#include <cuda_bf16.h>
#include <math.h>
#include <stdint.h>

// ---------------- problem constants ----------------
#define N_EMBD   2048
#define N_HEAD   16
#define HEAD_DIM 128
#define N_INNER  8192
#define SEQ      2048
#define BATCH    2
#define ROWS     (BATCH*SEQ)     /* 4096 */
#define QKV_W    (3*N_EMBD)      /* 6144 */
#define GRIDP    296             /* persistent CTAs: 2 per SM x 148 */

typedef __nv_bfloat16 bf16;
typedef __nv_bfloat162 bf162;

// ---------------- scratch (device globals; no allocs allowed) --------------
// TB8 (int8): [rowblk128][kchunk64] 16KB blocks; row=128B=[hi 64B|lo 64B],
//   16B unit u at r*128 + ((u^(r&7))<<4)  (u0..3 = hi k0..63, u4..7 = lo)
// TB  (bf16): [rowblk128][kchunk32] 16KB blocks; same swizzle
// AB  (bf16 attention): [type][b][h][seqblk64] 32KB blocks; row=512B,
//   unit u at r*512 + ((u^(r&7))<<4)  (u0..15 hi, 16..31 lo)
__device__ __align__(256) int8_t g_x8 [(size_t)ROWS * N_EMBD * 2];
__device__ __align__(256) int8_t g_a8 [(size_t)ROWS * N_EMBD * 2];
__device__ __align__(256) int8_t g_f8 [(size_t)ROWS * N_INNER * 2];
__device__ __align__(256) int8_t g_wq8[(size_t)QKV_W * N_EMBD * 2];
__device__ __align__(256) int8_t g_wp8[(size_t)N_EMBD * N_EMBD * 2];
__device__ __align__(256) int8_t g_wf8[(size_t)N_INNER * N_EMBD * 2];
__device__ __align__(256) int8_t g_wm8[(size_t)N_EMBD * N_INNER * 2];
__device__ __align__(256) bf16   g_a  [(size_t)ROWS * N_EMBD * 2];
__device__ __align__(256) bf16   g_f  [(size_t)ROWS * N_INNER * 2];
__device__ __align__(256) bf16   g_qt [(size_t)3 * BATCH * N_HEAD * 32 * 16384];
__device__ float g_hid[(size_t)ROWS * N_EMBD];
__device__ float g_sA [N_EMBD];
__device__ float g_sM [N_INNER];
__device__ float g_sx [ROWS];
__device__ float g_sa [ROWS];
__device__ float g_sf [ROWS];
__device__ float g_swq[QKV_W];
__device__ float g_swp[N_EMBD];
__device__ float g_swf[N_INNER];
__device__ float g_swm[N_EMBD];
__device__ float g_rma[ROWS];
__device__ float g_rmf[ROWS];
__device__ float g_cn [8 * N_INNER];   // colnorm partials (deterministic)

// ========================= helpers =========================================
__device__ __forceinline__ uint32_t smem_u32(const void* p) {
    uint32_t a;
    asm("{ .reg .u64 t; cvta.to.shared.u64 t, %1; cvt.u32.u64 %0, t; }"
        : "=r"(a) : "l"(p));
    return a;
}
__device__ __forceinline__ uint32_t tb_off(int r, int u) {
    return (uint32_t)(r * 128 + ((u ^ (r & 7)) << 4));
}
__device__ __forceinline__ uint32_t ab_off(int r, int u) {
    return (uint32_t)(r * 512 + ((u ^ (r & 7)) << 4));
}
__device__ __forceinline__ void mbar_init(uint32_t m, uint32_t cnt) {
    asm volatile("mbarrier.init.shared.b64 [%0], %1;" :: "r"(m), "r"(cnt) : "memory");
}
__device__ __forceinline__ void mbar_expect(uint32_t m, uint32_t bytes) {
    asm volatile("mbarrier.arrive.expect_tx.shared.b64 _, [%0], %1;"
                 :: "r"(m), "r"(bytes) : "memory");
}
__device__ __forceinline__ void mbar_arrive(uint32_t m) {
    asm volatile("mbarrier.arrive.shared.b64 _, [%0];" :: "r"(m) : "memory");
}
__device__ __forceinline__ void mbar_wait(uint32_t m, uint32_t parity) {
    asm volatile(
        "{\n\t.reg .pred P;\n\t"
        "W_%=:\n\t"
        "mbarrier.try_wait.parity.shared.b64 P, [%0], %1;\n\t"
        "@!P bra W_%=;\n\t}"
        :: "r"(m), "r"(parity) : "memory");
}
__device__ __forceinline__ void bulk_g2s(uint32_t dst, const void* src,
                                         uint32_t bytes, uint32_t mbar) {
    asm volatile(
        "cp.async.bulk.shared::cluster.global.mbarrier::complete_tx::bytes "
        "[%0], [%1], %2, [%3];"
        :: "r"(dst), "l"(src), "r"(bytes), "r"(mbar) : "memory");
}
__device__ __forceinline__ void ldsm4(uint32_t& r0, uint32_t& r1,
                                      uint32_t& r2, uint32_t& r3, uint32_t addr) {
    asm volatile("ldmatrix.sync.aligned.m8n8.x4.shared.b16 {%0,%1,%2,%3}, [%4];"
                 : "=r"(r0), "=r"(r1), "=r"(r2), "=r"(r3) : "r"(addr));
}
__device__ __forceinline__ void ldsm4t(uint32_t& r0, uint32_t& r1,
                                       uint32_t& r2, uint32_t& r3, uint32_t addr) {
    asm volatile("ldmatrix.sync.aligned.m8n8.x4.trans.shared.b16 {%0,%1,%2,%3}, [%4];"
                 : "=r"(r0), "=r"(r1), "=r"(r2), "=r"(r3) : "r"(addr));
}
__device__ __forceinline__ void mma_bf16(float* c, const uint32_t* a,
                                         const uint32_t* b) {
    asm volatile(
        "mma.sync.aligned.m16n8k16.row.col.f32.bf16.bf16.f32 "
        "{%0,%1,%2,%3}, {%4,%5,%6,%7}, {%8,%9}, {%0,%1,%2,%3};"
        : "+f"(c[0]), "+f"(c[1]), "+f"(c[2]), "+f"(c[3])
        : "r"(a[0]), "r"(a[1]), "r"(a[2]), "r"(a[3]), "r"(b[0]), "r"(b[1]));
}
__device__ __forceinline__ void mma_s8(int* c, const uint32_t* a,
                                       const uint32_t* b) {
    asm volatile(
        "mma.sync.aligned.m16n8k32.row.col.s32.s8.s8.s32 "
        "{%0,%1,%2,%3}, {%4,%5,%6,%7}, {%8,%9}, {%0,%1,%2,%3};"
        : "+r"(c[0]), "+r"(c[1]), "+r"(c[2]), "+r"(c[3])
        : "r"(a[0]), "r"(a[1]), "r"(a[2]), "r"(a[3]), "r"(b[0]), "r"(b[1]));
}
__device__ __forceinline__ float ex2f(float x) {
    float y;
    asm("ex2.approx.f32 %0, %1;" : "=f"(y) : "f"(x));
    return y;
}
__device__ __forceinline__ void split2(float x, bf16& h, bf16& l) {
    h = __float2bfloat16(x);
    l = __float2bfloat16(x - __bfloat162float(h));
}
__device__ __forceinline__ uint32_t packbf(float a, float b) {
    bf162 t = __floats2bfloat162_rn(a, b);
    return *(uint32_t*)&t;
}
__device__ __forceinline__ uint32_t packs8(int a, int b, int c, int d) {
    return (uint32_t)(a & 255) | ((uint32_t)(b & 255) << 8) |
           ((uint32_t)(c & 255) << 16) | ((uint32_t)(d & 255) << 24);
}
__device__ __forceinline__ void quant2(float x, float inv, int& qh, int& ql) {
    const float xh = x * inv;                 // |xh| <= 127
    qh = __float2int_rn(xh);
    ql = __float2int_rn((xh - (float)qh) * 254.f);
}
__device__ __forceinline__ float blockmax256(float v, float* red, int t) {
#pragma unroll
    for (int o = 16; o > 0; o >>= 1) v = fmaxf(v, __shfl_xor_sync(0xffffffffu, v, o));
    if ((t & 31) == 0) red[t >> 5] = v;
    __syncthreads();
    float m = red[0];
#pragma unroll
    for (int i = 1; i < 8; i++) m = fmaxf(m, red[i]);
    return m;
}

// ======================= LayerNorm -> int8 TB8 + scale (+zero rowmax) ======
__global__ __launch_bounds__(256) void ln8_kernel(const float* __restrict__ x,
                                                  const float* __restrict__ g,
                                                  const float* __restrict__ bp,
                                                  int8_t* __restrict__ yt,
                                                  float* __restrict__ sArr,
                                                  float* __restrict__ zp) {
    __shared__ float red[8];
    __shared__ float s_mean, s_rstd;
    const int row = blockIdx.x, t = threadIdx.x;
    if (t == 0) zp[row] = 0.f;      // zero rowmax accumulator for later stage
    const float* xr = x + (size_t)row * N_EMBD + t * 8;
    float v[8];
    *(float4*)&v[0] = *(const float4*)&xr[0];
    *(float4*)&v[4] = *(const float4*)&xr[4];
    float s = v[0] + v[1] + v[2] + v[3] + v[4] + v[5] + v[6] + v[7];
#pragma unroll
    for (int o = 16; o > 0; o >>= 1) s += __shfl_xor_sync(0xffffffffu, s, o);
    if ((t & 31) == 0) red[t >> 5] = s;
    __syncthreads();
    if (t == 0) {
        float tt = 0.f;
#pragma unroll
        for (int i = 0; i < 8; i++) tt += red[i];
        s_mean = tt * (1.f / N_EMBD);
    }
    __syncthreads();
    const float mu = s_mean;
    float vs = 0.f;
#pragma unroll
    for (int k = 0; k < 8; k++) { float d = v[k] - mu; vs += d * d; }
#pragma unroll
    for (int o = 16; o > 0; o >>= 1) vs += __shfl_xor_sync(0xffffffffu, vs, o);
    if ((t & 31) == 0) red[t >> 5] = vs;
    __syncthreads();
    if (t == 0) {
        float tt = 0.f;
#pragma unroll
        for (int i = 0; i < 8; i++) tt += red[i];
        s_rstd = rsqrtf(tt * (1.f / N_EMBD) + 1e-5f);
    }
    __syncthreads();
    const float rstd = s_rstd;
    float gg[8], bb[8];
    *(float4*)&gg[0] = *(const float4*)&g[t * 8];
    *(float4*)&gg[4] = *(const float4*)&g[t * 8 + 4];
    *(float4*)&bb[0] = *(const float4*)&bp[t * 8];
    *(float4*)&bb[4] = *(const float4*)&bp[t * 8 + 4];
    float val[8];
    float mx = 0.f;
#pragma unroll
    for (int k = 0; k < 8; k++) {
        val[k] = (v[k] - mu) * rstd * gg[k] + bb[k];
        mx = fmaxf(mx, fabsf(val[k]));
    }
    __syncthreads();   // red[] reuse
    const float gmax = fmaxf(blockmax256(mx, red, t), 1e-20f);
    const float inv = 127.f / gmax;
    if (t == 0) sArr[row] = gmax * (1.f / 127.f);
    int qh[8], ql[8];
#pragma unroll
    for (int k = 0; k < 8; k++) quant2(val[k], inv, qh[k], ql[k]);
    uint2 H, L;
    H.x = packs8(qh[0], qh[1], qh[2], qh[3]);
    H.y = packs8(qh[4], qh[5], qh[6], qh[7]);
    L.x = packs8(ql[0], ql[1], ql[2], ql[3]);
    L.y = packs8(ql[4], ql[5], ql[6], ql[7]);
    const int mblk = row >> 7, rl = row & 127;
    const int c = t >> 3, u = (t >> 1) & 3, intra = (t & 1) * 8;
    char* base = (char*)yt + (((size_t)(mblk * 32 + c)) << 14);
    *(uint2*)(base + tb_off(rl, u) + intra)     = H;
    *(uint2*)(base + tb_off(rl, u + 4) + intra) = L;
}

// ========== weight-norm column sumsq: deterministic split-K ================
// grid (cols/32, 8). Each block writes one partial (no atomics).
__global__ __launch_bounds__(256) void colnorm_part(const float* __restrict__ v,
                                                    float* __restrict__ tmp,
                                                    int rows, int cols) {
    __shared__ float red[8][32];
    const int lane = threadIdx.x & 31;
    const int w    = threadIdx.x >> 5;
    const int j    = blockIdx.x * 32 + lane;
    const int rs   = rows >> 3;
    const int r0   = blockIdx.y * rs;
    float acc = 0.f;
    for (int r = r0 + w; r < r0 + rs; r += 8) {
        float t = v[(size_t)r * cols + j];
        acc += t * t;
    }
    red[w][lane] = acc;
    __syncthreads();
    if (w == 0) {
        float s = red[0][lane];
#pragma unroll
        for (int q = 1; q < 8; q++) s += red[q][lane];
        tmp[(size_t)blockIdx.y * cols + j] = s;
    }
}
__global__ __launch_bounds__(256) void colnorm_fin(const float* __restrict__ tmp,
                                                   const float* __restrict__ g,
                                                   float* __restrict__ scale,
                                                   int cols) {
    const int j = blockIdx.x * 256 + threadIdx.x;
    float s = 0.f;
#pragma unroll
    for (int i = 0; i < 8; i++) s += tmp[(size_t)i * cols + j];
    scale[j] = g[j] / sqrtf(s);
}

// ========== weight conversion: fp32 (* s[k]) -> int8 TB8 + scale ===========
__global__ __launch_bounds__(256) void convw8_kernel(const float* __restrict__ w,
                                                     const float* __restrict__ s,
                                                     int8_t* __restrict__ out,
                                                     float* __restrict__ sArr,
                                                     int K) {
    __shared__ float red[8];
    const int n = blockIdx.x, t = threadIdx.x;
    const int groups = K >> 11;          // 1 or 4
    float val[32];
    float mx = 0.f;
    for (int gq = 0; gq < groups; gq++) {
        const int k = gq * 2048 + t * 8;
        float vv[8];
        *(float4*)&vv[0] = *(const float4*)&w[(size_t)n * K + k];
        *(float4*)&vv[4] = *(const float4*)&w[(size_t)n * K + k + 4];
        if (s) {
#pragma unroll
            for (int q = 0; q < 8; q++) vv[q] *= s[k + q];
        }
#pragma unroll
        for (int q = 0; q < 8; q++) {
            val[gq * 8 + q] = vv[q];
            mx = fmaxf(mx, fabsf(vv[q]));
        }
    }
    const float gmax = fmaxf(blockmax256(mx, red, t), 1e-20f);
    const float inv = 127.f / gmax;
    if (t == 0) sArr[n] = gmax * (1.f / 127.f);
    const int nblk = n >> 7, rl = n & 127, nc = K >> 6;
    for (int gq = 0; gq < groups; gq++) {
        const int k = gq * 2048 + t * 8;
        int qh[8], ql[8];
#pragma unroll
        for (int q = 0; q < 8; q++) quant2(val[gq * 8 + q], inv, qh[q], ql[q]);
        uint2 H, L;
        H.x = packs8(qh[0], qh[1], qh[2], qh[3]);
        H.y = packs8(qh[4], qh[5], qh[6], qh[7]);
        L.x = packs8(ql[0], ql[1], ql[2], ql[3]);
        L.y = packs8(ql[4], ql[5], ql[6], ql[7]);
        const int c = k >> 6, u = (k >> 4) & 3, intra = k & 15;
        char* base = (char*)out + (((size_t)(nblk * nc + c)) << 14);
        *(uint2*)(base + tb_off(rl, u) + intra)     = H;
        *(uint2*)(base + tb_off(rl, u + 4) + intra) = L;
    }
}

// ========== convert: bf16 TB -> int8 TB8 using atomic rowmax ===============
__global__ __launch_bounds__(256) void convert8_kernel(const bf16* __restrict__ src,
                                                       int8_t* __restrict__ dst,
                                                       const float* __restrict__ rm,
                                                       float* __restrict__ sArr,
                                                       int K) {
    const int row = blockIdx.x, t = threadIdx.x;
    const int groups = K >> 11;
    const float gmax = fmaxf(rm[row], 1e-20f);
    const float inv = 127.f / gmax;
    if (t == 0) sArr[row] = gmax * (1.f / 127.f);
    const int mblk = row >> 7, rl = row & 127;
    const int nc16 = K >> 5, nc8 = K >> 6;
    for (int gq = 0; gq < groups; gq++) {
        const int k = gq * 2048 + t * 8;
        const char* sblk = (const char*)src + (((size_t)(mblk * nc16 + (k >> 5))) << 14);
        const int u16 = (k >> 3) & 3;
        uint4 Hh = *(const uint4*)(sblk + tb_off(rl, u16));
        uint4 Ll = *(const uint4*)(sblk + tb_off(rl, u16 + 4));
        const uint32_t* hw = (const uint32_t*)&Hh;
        const uint32_t* lw = (const uint32_t*)&Ll;
        int qh[8], ql[8];
#pragma unroll
        for (int q = 0; q < 4; q++) {
            bf162 hb = *(const bf162*)&hw[q];
            bf162 lb = *(const bf162*)&lw[q];
            const float v0 = __bfloat162float(hb.x) + __bfloat162float(lb.x);
            const float v1 = __bfloat162float(hb.y) + __bfloat162float(lb.y);
            quant2(v0, inv, qh[2 * q], ql[2 * q]);
            quant2(v1, inv, qh[2 * q + 1], ql[2 * q + 1]);
        }
        uint2 H, L;
        H.x = packs8(qh[0], qh[1], qh[2], qh[3]);
        H.y = packs8(qh[4], qh[5], qh[6], qh[7]);
        L.x = packs8(ql[0], ql[1], ql[2], ql[3]);
        L.y = packs8(ql[4], ql[5], ql[6], ql[7]);
        char* base = (char*)dst + (((size_t)(mblk * nc8 + (k >> 6))) << 14);
        const int u = (k >> 4) & 3, intra = k & 15;
        *(uint2*)(base + tb_off(rl, u) + intra)     = H;
        *(uint2*)(base + tb_off(rl, u + 4) + intra) = L;
    }
}

// ===== persistent split-int8 IMMA GEMM: 128x64 tiles, continuous pipeline ==
// grid = GRIDP (2 CTAs/SM). Each CTA walks tiles bx, bx+G, ... with a single
// chunk-indexed loop; the 4-stage pipeline never drains across tiles.
// 256 thr = 8 warps (4m x 2n), warp tile 32x32.
// D = sA[m]*sB[n]*(accHH + accX/254) + epilogue.
#define GSOFF 1024
#define GSTG  24576
#define GSTAGES 4
#define GEMM_SMEM (GSOFF + GSTAGES * GSTG)

template<bool DOGELU, bool RES, bool WF32, bool WTB, bool WQKV>
__global__ __launch_bounds__(256, 2) void tgemm8(const int8_t* __restrict__ A,
                                                 const int8_t* __restrict__ B,
                                                 const float* __restrict__ sA,
                                                 const float* __restrict__ sB,
                                                 const float* __restrict__ bias,
                                                 const float* __restrict__ res,
                                                 float* __restrict__ C,
                                                 bf16* __restrict__ T,
                                                 float* __restrict__ rmax,
                                                 int M, int N, int K) {
    extern __shared__ char sm[];
    const uint32_t sb = smem_u32(sm);
    const int tid  = threadIdx.x;
    const int lane = tid & 31;
    const int wid  = tid >> 5;
    const int warp_m = wid >> 1;    // 0..3 -> 32-row slice
    const int warp_n = wid & 1;     // 0..1 -> 32-col half
    const int nx = N >> 6;
    const int ntiles = (M >> 7) * nx;
    const int nc = K >> 6;          // 32 or 128 (power of two)
    const int ncm1 = nc - 1;
    const int lgnc = __ffs(nc) - 1;
    const int G = gridDim.x, bx = blockIdx.x;
    const int mytiles = (ntiles - bx + G - 1) / G;
    const int total = mytiles * nc;
    const int lm = lane & 15, lq = lane >> 4, l8 = (lane >> 3) & 1, l7 = lane & 7;
    const char* Ab = (const char*)A;
    const char* Bb = (const char*)B;

    if (tid == 0) {
#pragma unroll
        for (int s = 0; s < GSTAGES; s++) {
            mbar_init(sb + s * 8, 1);
            mbar_init(sb + 32 + s * 8, 8);
        }
    }
    __syncthreads();

    auto prefetch = [&](int q, int slot) {
        const int ti = q >> lgnc, c = q & ncm1;
        const int tile = bx + ti * G;
        const int tx = tile % nx, ty = tile / nx;
        const uint32_t mb = sb + slot * 8;
        const uint32_t st = sb + GSOFF + slot * GSTG;
        mbar_expect(mb, 24576);
        bulk_g2s(st,         Ab + (((size_t)ty * nc + c) << 14), 16384, mb);
        bulk_g2s(st + 16384, Bb + (((size_t)(tx >> 1) * nc + c) << 14) +
                              (uint32_t)((tx & 1) * 8192), 8192, mb);
    };
    if (tid == 0) {
        const int np = total < GSTAGES ? total : GSTAGES;
        for (int s = 0; s < np; s++) prefetch(s, s);
    }

    int aH[2][4][4], aX[2][4][4];
#pragma unroll
    for (int i = 0; i < 2; i++)
#pragma unroll
        for (int j = 0; j < 4; j++)
#pragma unroll
            for (int t = 0; t < 4; t++) { aH[i][j][t] = 0; aX[i][j][t] = 0; }

    for (int q = 0; q < total; q++) {
        const int slot = q & 3;
        const int rnd  = q >> 2;
        mbar_wait(sb + slot * 8, rnd & 1);
        const uint32_t st = sb + GSOFF + slot * GSTG;
#pragma unroll
        for (int s = 0; s < 2; s++) {
            uint32_t bh[4][2], bl[4][2];
#pragma unroll
            for (int j2 = 0; j2 < 2; j2++) {
                const int r = warp_n * 32 + j2 * 16 + lq * 8 + l7;
                uint32_t t0, t1, t2, t3;
                ldsm4(t0, t1, t2, t3, st + 16384 + tb_off(r, s * 2 + l8));
                bh[2 * j2][0] = t0; bh[2 * j2][1] = t1;
                bh[2 * j2 + 1][0] = t2; bh[2 * j2 + 1][1] = t3;
                ldsm4(t0, t1, t2, t3, st + 16384 + tb_off(r, s * 2 + l8 + 4));
                bl[2 * j2][0] = t0; bl[2 * j2][1] = t1;
                bl[2 * j2 + 1][0] = t2; bl[2 * j2 + 1][1] = t3;
            }
#pragma unroll
            for (int i = 0; i < 2; i++) {
                const int rl = warp_m * 32 + lm + i * 16;
                uint32_t ah[4], al[4];
                ldsm4(ah[0], ah[1], ah[2], ah[3], st + tb_off(rl, s * 2 + lq));
                ldsm4(al[0], al[1], al[2], al[3], st + tb_off(rl, s * 2 + lq + 4));
#pragma unroll
                for (int j = 0; j < 4; j++) {
                    mma_s8(aH[i][j], ah, bh[j]);
                    mma_s8(aX[i][j], ah, bl[j]);
                    mma_s8(aX[i][j], al, bh[j]);
                }
            }
        }
        if (lane == 0) mbar_arrive(sb + 32 + slot * 8);
        if (tid == 0 && q + GSTAGES < total) {
            mbar_wait(sb + 32 + slot * 8, rnd & 1);
            prefetch(q + GSTAGES, slot);
        }

        if ((q & ncm1) == ncm1) {
            // ---------------- per-tile epilogue (pipeline keeps running) ---
            const int tile = bx + (q >> lgnc) * G;
            const int tx = tile % nx, ty = tile / nx;
            const int m0 = ty << 7, n0 = tx << 6;
            const float i254 = 1.f / 254.f;
            const int r_base = m0 + warp_m * 32 + (lane >> 2);
            const int c_base = n0 + warp_n * 32 + 2 * (lane & 3);
            float sAv[4];
#pragma unroll
            for (int i = 0; i < 2; i++) {
                sAv[2 * i]     = sA[r_base + i * 16];
                sAv[2 * i + 1] = sA[r_base + i * 16 + 8];
            }
            float rmx[4];
#pragma unroll
            for (int i = 0; i < 4; i++) rmx[i] = 0.f;
#pragma unroll
            for (int j = 0; j < 4; j++) {
                const int col = c_base + j * 8;
                const float2 bi = *(const float2*)&bias[col];
                const float2 sb2 = *(const float2*)&sB[col];
#pragma unroll
                for (int i = 0; i < 2; i++) {
#pragma unroll
                    for (int half = 0; half < 2; half++) {
                        const int row = r_base + i * 16 + half * 8;
                        const float sa = sAv[2 * i + half];
                        float vx = ((float)aH[i][j][half * 2 + 0] +
                                    (float)aX[i][j][half * 2 + 0] * i254) * (sa * sb2.x) + bi.x;
                        float vy = ((float)aH[i][j][half * 2 + 1] +
                                    (float)aX[i][j][half * 2 + 1] * i254) * (sa * sb2.y) + bi.y;
                        if (DOGELU) {
                            vx = 0.5f * vx * (1.f + erff(vx * 0.70710678118654752f));
                            vy = 0.5f * vy * (1.f + erff(vy * 0.70710678118654752f));
                        }
                        if (RES) {
                            const float2 rv = *(const float2*)&res[(size_t)row * N + col];
                            vx += rv.x; vy += rv.y;
                        }
                        if (WF32) {
                            float2 o; o.x = vx; o.y = vy;
                            *(float2*)&C[(size_t)row * N + col] = o;
                        }
                        if (WTB) {
                            rmx[2 * i + half] = fmaxf(rmx[2 * i + half],
                                                      fmaxf(fabsf(vx), fabsf(vy)));
                            bf16 h0, h1, l0, l1;
                            split2(vx, h0, l0); split2(vy, h1, l1);
                            bf162 ph; ph.x = h0; ph.y = h1;
                            bf162 pl; pl.x = l0; pl.y = l1;
                            const int mblk = row >> 7, rl = row & 127;
                            const int cc = col >> 5, u = (col & 31) >> 3, bo = (col & 7) * 2;
                            char* base = (char*)T + (((size_t)(mblk * (N >> 5) + cc)) << 14);
                            *(bf162*)(base + tb_off(rl, u) + bo)     = ph;
                            *(bf162*)(base + tb_off(rl, u + 4) + bo) = pl;
                        }
                        if (WQKV) {
                            bf16 h0, h1, l0, l1;
                            split2(vx, h0, l0); split2(vy, h1, l1);
                            bf162 ph; ph.x = h0; ph.y = h1;
                            bf162 pl; pl.x = l0; pl.y = l1;
                            const int type = col >> 11, hh = (col >> 7) & 15;
                            const int bb2 = row >> 11, seq = row & 2047;
                            const int sblk = seq >> 6, rl = seq & 63;
                            const int d = col & 127, u = d >> 3, bo = (d & 7) * 2;
                            char* base = (char*)T +
                                (((size_t)((((type * 2 + bb2) * 16 + hh) * 32) + sblk)) << 15);
                            *(bf162*)(base + ab_off(rl, u) + bo)      = ph;
                            *(bf162*)(base + ab_off(rl, u + 16) + bo) = pl;
                        }
                    }
                }
            }
            if (WTB) {
#pragma unroll
                for (int i = 0; i < 4; i++) {
                    float m = rmx[i];
                    m = fmaxf(m, __shfl_xor_sync(0xffffffffu, m, 1));
                    m = fmaxf(m, __shfl_xor_sync(0xffffffffu, m, 2));
                    if ((lane & 3) == 0) {
                        const int row = r_base + (i >> 1) * 16 + (i & 1) * 8;
                        atomicMax((int*)&rmax[row], __float_as_int(m));
                    }
                }
            }
            // reset accumulators for next tile
#pragma unroll
            for (int i = 0; i < 2; i++)
#pragma unroll
                for (int j = 0; j < 4; j++)
#pragma unroll
                    for (int t = 0; t < 4; t++) { aH[i][j][t] = 0; aX[i][j][t] = 0; }
        }
    }
}

// ============== HMMA split-bf16 flash attention (unchanged) ================
#define ASQ   1024
#define ASKV  (1024 + 65536)
#define ASTG  65536
#define ATT_SMEM (1024 + 65536 + 2 * 65536)
#define SOFTSC 0.1275174048f /* (1/sqrt(128)) * log2(e) */

__global__ __launch_bounds__(256) void attn_mma(const bf16* __restrict__ qt,
                                                bf16* __restrict__ aout,
                                                float* __restrict__ rmax) {
    extern __shared__ char sm[];
    const uint32_t sb = smem_u32(sm);
    const int tid  = threadIdx.x;
    const int lane = tid & 31;
    const int wid  = tid >> 5;
    const int qb   = blockIdx.x * 128;
    const int h    = blockIdx.y;
    const int b    = blockIdx.z;
    const int q0   = wid * 16;
    const int lm = lane & 15, lq = lane >> 4, l8 = (lane >> 3) & 1, l7 = lane & 7;
    const char* qbase = (const char*)qt;

    auto blk = [&](int type, int sblk) -> const char* {
        return qbase + (((size_t)(((type * 2 + b) * 16 + h) * 32 + sblk)) << 15);
    };

    if (tid == 0) {
        mbar_init(sb + 0, 1);
        mbar_init(sb + 8, 1);
        mbar_init(sb + 16, 1);
        mbar_init(sb + 24, 8);
        mbar_init(sb + 32, 8);
    }
    __syncthreads();
    if (tid == 0) {
        mbar_expect(sb + 0, 65536);
        bulk_g2s(sb + ASQ,          blk(0, (qb >> 6) + 0), 32768, sb + 0);
        bulk_g2s(sb + ASQ + 32768,  blk(0, (qb >> 6) + 1), 32768, sb + 0);
        mbar_expect(sb + 8, 65536);
        bulk_g2s(sb + ASKV,          blk(1, 0), 32768, sb + 8);
        bulk_g2s(sb + ASKV + 32768,  blk(2, 0), 32768, sb + 8);
        mbar_expect(sb + 16, 65536);
        bulk_g2s(sb + ASKV + ASTG,          blk(1, 1), 32768, sb + 16);
        bulk_g2s(sb + ASKV + ASTG + 32768,  blk(2, 1), 32768, sb + 16);
    }

    float m0 = -1e30f, m1 = -1e30f, l0 = 0.f, l1 = 0.f;
    float O[16][4];
#pragma unroll
    for (int f = 0; f < 16; f++)
#pragma unroll
        for (int c = 0; c < 4; c++) O[f][c] = 0.f;

    mbar_wait(sb + 0, 0);

    const int qr = q0 + lm;
    const uint32_t qblk = sb + ASQ + ((uint32_t)(qr >> 6) << 15);
    const int qrl = qr & 63;

    for (int it = 0; it < 32; it++) {
        const int slot = it & 1;
        const int rnd  = it >> 1;
        mbar_wait(sb + 8 + slot * 8, rnd & 1);
        const uint32_t kvb = sb + ASKV + slot * ASTG;

        float s[8][4];
#pragma unroll
        for (int j = 0; j < 8; j++)
#pragma unroll
            for (int c = 0; c < 4; c++) s[j][c] = 0.f;

#pragma unroll
        for (int kd = 0; kd < 8; kd++) {
            uint32_t aH[4], aL[4];
            ldsm4(aH[0], aH[1], aH[2], aH[3], qblk + ab_off(qrl, kd * 2 + lq));
            ldsm4(aL[0], aL[1], aL[2], aL[3], qblk + ab_off(qrl, kd * 2 + lq + 16));
#pragma unroll
            for (int kg = 0; kg < 4; kg++) {
                const int kr = kg * 16 + lq * 8 + l7;
                uint32_t t0, t1, t2, t3;
                uint32_t bh0[2], bh1[2], bl0[2], bl1[2];
                ldsm4(t0, t1, t2, t3, kvb + ab_off(kr, kd * 2 + l8));
                bh0[0] = t0; bh0[1] = t1; bh1[0] = t2; bh1[1] = t3;
                ldsm4(t0, t1, t2, t3, kvb + ab_off(kr, kd * 2 + l8 + 16));
                bl0[0] = t0; bl0[1] = t1; bl1[0] = t2; bl1[1] = t3;
                mma_bf16(s[2 * kg],     aH, bh0);
                mma_bf16(s[2 * kg],     aH, bl0);
                mma_bf16(s[2 * kg],     aL, bh0);
                mma_bf16(s[2 * kg + 1], aH, bh1);
                mma_bf16(s[2 * kg + 1], aH, bl1);
                mma_bf16(s[2 * kg + 1], aL, bh1);
            }
        }

        float mt0 = -1e30f, mt1 = -1e30f;
#pragma unroll
        for (int j = 0; j < 8; j++) {
#pragma unroll
            for (int c = 0; c < 4; c++) s[j][c] *= SOFTSC;
            mt0 = fmaxf(mt0, fmaxf(s[j][0], s[j][1]));
            mt1 = fmaxf(mt1, fmaxf(s[j][2], s[j][3]));
        }
        mt0 = fmaxf(mt0, __shfl_xor_sync(0xffffffffu, mt0, 1));
        mt0 = fmaxf(mt0, __shfl_xor_sync(0xffffffffu, mt0, 2));
        mt1 = fmaxf(mt1, __shfl_xor_sync(0xffffffffu, mt1, 1));
        mt1 = fmaxf(mt1, __shfl_xor_sync(0xffffffffu, mt1, 2));
        const float mn0 = fmaxf(m0, mt0), mn1 = fmaxf(m1, mt1);
        const float corr0 = ex2f(m0 - mn0), corr1 = ex2f(m1 - mn1);
        m0 = mn0; m1 = mn1;
        float ps0 = 0.f, ps1 = 0.f;
#pragma unroll
        for (int j = 0; j < 8; j++) {
            s[j][0] = ex2f(s[j][0] - mn0);
            s[j][1] = ex2f(s[j][1] - mn0);
            s[j][2] = ex2f(s[j][2] - mn1);
            s[j][3] = ex2f(s[j][3] - mn1);
            ps0 += s[j][0] + s[j][1];
            ps1 += s[j][2] + s[j][3];
        }
        l0 = l0 * corr0 + ps0;
        l1 = l1 * corr1 + ps1;
#pragma unroll
        for (int f = 0; f < 16; f++) {
            O[f][0] *= corr0; O[f][1] *= corr0;
            O[f][2] *= corr1; O[f][3] *= corr1;
        }

#pragma unroll
        for (int kk = 0; kk < 4; kk++) {
            const int j0 = 2 * kk, j1 = 2 * kk + 1;
            uint32_t pH[4], pL[4];
            {
                uint32_t hi;
                bf162 hv;
                float la, lb;
                hi = packbf(s[j0][0], s[j0][1]); hv = *(bf162*)&hi;
                la = s[j0][0] - __bfloat162float(hv.x);
                lb = s[j0][1] - __bfloat162float(hv.y);
                pH[0] = hi; pL[0] = packbf(la, lb);
                hi = packbf(s[j0][2], s[j0][3]); hv = *(bf162*)&hi;
                la = s[j0][2] - __bfloat162float(hv.x);
                lb = s[j0][3] - __bfloat162float(hv.y);
                pH[1] = hi; pL[1] = packbf(la, lb);
                hi = packbf(s[j1][0], s[j1][1]); hv = *(bf162*)&hi;
                la = s[j1][0] - __bfloat162float(hv.x);
                lb = s[j1][1] - __bfloat162float(hv.y);
                pH[2] = hi; pL[2] = packbf(la, lb);
                hi = packbf(s[j1][2], s[j1][3]); hv = *(bf162*)&hi;
                la = s[j1][2] - __bfloat162float(hv.x);
                lb = s[j1][3] - __bfloat162float(hv.y);
                pH[3] = hi; pL[3] = packbf(la, lb);
            }
#pragma unroll
            for (int g = 0; g < 8; g++) {
                const int vr = kk * 16 + l8 * 8 + l7;
                uint32_t t0, t1, t2, t3;
                uint32_t bh0[2], bh1[2], bl0[2], bl1[2];
                ldsm4t(t0, t1, t2, t3, kvb + 32768 + ab_off(vr, g * 2 + lq));
                bh0[0] = t0; bh0[1] = t1; bh1[0] = t2; bh1[1] = t3;
                ldsm4t(t0, t1, t2, t3, kvb + 32768 + ab_off(vr, g * 2 + lq + 16));
                bl0[0] = t0; bl0[1] = t1; bl1[0] = t2; bl1[1] = t3;
                mma_bf16(O[2 * g],     pH, bh0);
                mma_bf16(O[2 * g],     pH, bl0);
                mma_bf16(O[2 * g],     pL, bh0);
                mma_bf16(O[2 * g + 1], pH, bh1);
                mma_bf16(O[2 * g + 1], pH, bl1);
                mma_bf16(O[2 * g + 1], pL, bh1);
            }
        }
        if (lane == 0) mbar_arrive(sb + 24 + slot * 8);
        if (tid == 0 && it + 2 < 32) {
            mbar_wait(sb + 24 + slot * 8, rnd & 1);
            const uint32_t mb = sb + 8 + slot * 8;
            const uint32_t dst = sb + ASKV + slot * ASTG;
            mbar_expect(mb, 65536);
            bulk_g2s(dst,         blk(1, it + 2), 32768, mb);
            bulk_g2s(dst + 32768, blk(2, it + 2), 32768, mb);
        }
    }

    l0 += __shfl_xor_sync(0xffffffffu, l0, 1);
    l0 += __shfl_xor_sync(0xffffffffu, l0, 2);
    l1 += __shfl_xor_sync(0xffffffffu, l1, 1);
    l1 += __shfl_xor_sync(0xffffffffu, l1, 2);
    const float inv0 = 1.f / l0, inv1 = 1.f / l1;
    const int r0g = b * SEQ + qb + q0 + (lane >> 2);
    const int r1g = r0g + 8;
    const int col0 = h * HEAD_DIM + 2 * (lane & 3);
    char* ga = (char*)aout;
    float mx0 = 0.f, mx1 = 0.f;
#pragma unroll
    for (int f = 0; f < 16; f++) {
        const int col = col0 + f * 8;
        const int c = col >> 5, u = (col & 31) >> 3, bo = (col & 7) * 2;
#pragma unroll
        for (int half = 0; half < 2; half++) {
            const int row = half ? r1g : r0g;
            const float inv = half ? inv1 : inv0;
            const float vx = O[f][half * 2 + 0] * inv;
            const float vy = O[f][half * 2 + 1] * inv;
            const float am = fmaxf(fabsf(vx), fabsf(vy));
            if (half) mx1 = fmaxf(mx1, am); else mx0 = fmaxf(mx0, am);
            bf16 h0, h1, lo0, lo1;
            split2(vx, h0, lo0); split2(vy, h1, lo1);
            bf162 ph; ph.x = h0; ph.y = h1;
            bf162 pl; pl.x = lo0; pl.y = lo1;
            const int mblk = row >> 7, rl = row & 127;
            char* base = ga + (((size_t)(mblk * 64 + c)) << 14);
            *(bf162*)(base + tb_off(rl, u) + bo)     = ph;
            *(bf162*)(base + tb_off(rl, u + 4) + bo) = pl;
        }
    }
    mx0 = fmaxf(mx0, __shfl_xor_sync(0xffffffffu, mx0, 1));
    mx0 = fmaxf(mx0, __shfl_xor_sync(0xffffffffu, mx0, 2));
    mx1 = fmaxf(mx1, __shfl_xor_sync(0xffffffffu, mx1, 1));
    mx1 = fmaxf(mx1, __shfl_xor_sync(0xffffffffu, mx1, 2));
    if ((lane & 3) == 0) {
        atomicMax((int*)&rmax[r0g], __float_as_int(mx0));
        atomicMax((int*)&rmax[r1g], __float_as_int(mx1));
    }
}

// =========================== launch sequence ===============================
extern "C" void kernel_launch(void* const* d_in, const int* in_sizes, int n_in,
                              void* d_out, int out_size) {
    const float* hs      = (const float*)d_in[0];
    const float* ln1_g   = (const float*)d_in[1];
    const float* ln1_b   = (const float*)d_in[2];
    const float* w_qkv   = (const float*)d_in[3];
    const float* b_qkv   = (const float*)d_in[4];
    const float* attn_v  = (const float*)d_in[5];
    const float* attn_g  = (const float*)d_in[6];
    const float* attn_b  = (const float*)d_in[7];
    /* d_in[8] = emotion_bias: softmax-invariant, unused */
    const float* ln2_g   = (const float*)d_in[9];
    const float* ln2_b   = (const float*)d_in[10];
    const float* w_fc    = (const float*)d_in[11];
    const float* b_fc    = (const float*)d_in[12];
    const float* mlp_v   = (const float*)d_in[13];
    const float* mlp_g   = (const float*)d_in[14];
    const float* mlp_b   = (const float*)d_in[15];
    float* out = (float*)d_out;

    float *hid, *sA, *sM, *sx, *sa, *sf, *swq, *swp, *swf, *swm, *rma, *rmf, *cn;
    int8_t *x8, *a8, *f8, *wq8, *wp8, *wf8, *wm8;
    bf16 *at, *ft, *qt;
    cudaGetSymbolAddress((void**)&hid, g_hid);
    cudaGetSymbolAddress((void**)&sA,  g_sA);
    cudaGetSymbolAddress((void**)&sM,  g_sM);
    cudaGetSymbolAddress((void**)&sx,  g_sx);
    cudaGetSymbolAddress((void**)&sa,  g_sa);
    cudaGetSymbolAddress((void**)&sf,  g_sf);
    cudaGetSymbolAddress((void**)&swq, g_swq);
    cudaGetSymbolAddress((void**)&swp, g_swp);
    cudaGetSymbolAddress((void**)&swf, g_swf);
    cudaGetSymbolAddress((void**)&swm, g_swm);
    cudaGetSymbolAddress((void**)&rma, g_rma);
    cudaGetSymbolAddress((void**)&rmf, g_rmf);
    cudaGetSymbolAddress((void**)&cn,  g_cn);
    cudaGetSymbolAddress((void**)&x8,  g_x8);
    cudaGetSymbolAddress((void**)&a8,  g_a8);
    cudaGetSymbolAddress((void**)&f8,  g_f8);
    cudaGetSymbolAddress((void**)&wq8, g_wq8);
    cudaGetSymbolAddress((void**)&wp8, g_wp8);
    cudaGetSymbolAddress((void**)&wf8, g_wf8);
    cudaGetSymbolAddress((void**)&wm8, g_wm8);
    cudaGetSymbolAddress((void**)&at,  g_a);
    cudaGetSymbolAddress((void**)&ft,  g_f);
    cudaGetSymbolAddress((void**)&qt,  g_qt);

    cudaFuncSetAttribute(attn_mma,
                         cudaFuncAttributeMaxDynamicSharedMemorySize, ATT_SMEM);
    cudaFuncSetAttribute(tgemm8<false, false, false, false, true>,
                         cudaFuncAttributeMaxDynamicSharedMemorySize, GEMM_SMEM);
    cudaFuncSetAttribute(tgemm8<false, true, true, false, false>,
                         cudaFuncAttributeMaxDynamicSharedMemorySize, GEMM_SMEM);
    cudaFuncSetAttribute(tgemm8<true, false, false, true, false>,
                         cudaFuncAttributeMaxDynamicSharedMemorySize, GEMM_SMEM);

    // k0: LN1 -> int8 TB8 + scale (zeroes rma)
    ln8_kernel<<<ROWS, 256>>>(hs, ln1_g, ln1_b, x8, sx, rma);
    // k1: convw w_qkv -> int8 TB8
    convw8_kernel<<<QKV_W, 256>>>(w_qkv, nullptr, wq8, swq, N_EMBD);
    // k2: QKV GEMM (persistent int8) -> bf16 AB
    tgemm8<false, false, false, false, true><<<GRIDP, 256, GEMM_SMEM>>>(
        x8, wq8, sx, swq, b_qkv, nullptr, nullptr, qt, nullptr,
        ROWS, QKV_W, N_EMBD);
    // k3: attention -> bf16 TB + rowmax    (ncu capture target: harness slot 5)
    attn_mma<<<dim3(SEQ / 128, N_HEAD, BATCH), 256, ATT_SMEM>>>(qt, at, rma);
    // k4,k5: colnorm attn proj (deterministic split-K)
    colnorm_part<<<dim3(N_EMBD / 32, 8), 256>>>(attn_v, cn, N_EMBD, N_EMBD);
    colnorm_fin<<<N_EMBD / 256, 256>>>(cn, attn_g, sA, N_EMBD);
    // k6: convert attention output -> int8
    convert8_kernel<<<ROWS, 256>>>(at, a8, rma, sa, N_EMBD);
    // k7: convw attn proj (wn-folded) -> int8
    convw8_kernel<<<N_EMBD, 256>>>(attn_v, sA, wp8, swp, N_EMBD);
    // k8: attn proj + residual(hs) -> hid fp32
    tgemm8<false, true, true, false, false><<<GRIDP, 256, GEMM_SMEM>>>(
        a8, wp8, sa, swp, attn_b, hs, hid, nullptr, nullptr,
        ROWS, N_EMBD, N_EMBD);
    // k9: LN2 -> int8 (zeroes rmf)
    ln8_kernel<<<ROWS, 256>>>(hid, ln2_g, ln2_b, x8, sx, rmf);
    // k10: convw w_fc -> int8
    convw8_kernel<<<N_INNER, 256>>>(w_fc, nullptr, wf8, swf, N_EMBD);
    // k11: FC + GELU -> bf16 TB + rowmax
    tgemm8<true, false, false, true, false><<<GRIDP, 256, GEMM_SMEM>>>(
        x8, wf8, sx, swf, b_fc, nullptr, nullptr, ft, rmf,
        ROWS, N_INNER, N_EMBD);
    // k12: convert gelu output -> int8
    convert8_kernel<<<ROWS, 256>>>(ft, f8, rmf, sf, N_INNER);
    // k13,k14: colnorm mlp proj (deterministic split-K)
    colnorm_part<<<dim3(N_INNER / 32, 8), 256>>>(mlp_v, cn, N_EMBD, N_INNER);
    colnorm_fin<<<N_INNER / 256, 256>>>(cn, mlp_g, sM, N_INNER);
    // k15: convw mlp proj (wn-folded, K=8192) -> int8
    convw8_kernel<<<N_EMBD, 256>>>(mlp_v, sM, wm8, swm, N_INNER);
    // k16: MLP proj + residual(hid) -> out fp32
    tgemm8<false, true, true, false, false><<<GRIDP, 256, GEMM_SMEM>>>(
        f8, wm8, sf, swm, mlp_b, hid, out, nullptr, nullptr,
        ROWS, N_EMBD, N_INNER);
}